// round 9
// baseline (speedup 1.0000x reference)
#include <cuda_runtime.h>
#include <cuda_bf16.h>

#define BB 512
#define SS 1024
#define TT 64

typedef unsigned long long u64;

// ---- packed f32x2 helpers (Blackwell FFMA2 path) ----
__device__ __forceinline__ u64 fma2(u64 a, u64 b, u64 c) {
    u64 d;
    asm("fma.rn.f32x2 %0, %1, %2, %3;" : "=l"(d) : "l"(a), "l"(b), "l"(c));
    return d;
}
__device__ __forceinline__ u64 add2(u64 a, u64 b) {
    u64 d;
    asm("add.rn.f32x2 %0, %1, %2;" : "=l"(d) : "l"(a), "l"(b));
    return d;
}
__device__ __forceinline__ u64 pack2(float lo, float hi) {
    u64 d;
    asm("mov.b64 %0, {%1, %2};" : "=l"(d) : "f"(lo), "f"(hi));
    return d;
}
__device__ __forceinline__ void unpack2(u64 v, float& lo, float& hi) {
    asm("mov.b64 {%0, %1}, %2;" : "=f"(lo), "=f"(hi) : "l"(v));
}

// mask dtype modes
#define MM_I32 0
#define MM_F32 1
#define MM_U8  2

__device__ __forceinline__ int mask_at(const void* m, long long idx, int mode) {
    if (mode == MM_I32) return ((const int*)m)[idx] != 0;
    if (mode == MM_F32) return ((const float*)m)[idx] != 0.0f;
    return ((const unsigned char*)m)[idx] != 0;
}

__global__ __launch_bounds__(64)
void crf_loss_kernel(const int* __restrict__ tags,
                     const void* __restrict__ mask,
                     const float* __restrict__ emit,
                     const float* __restrict__ trans,
                     float* __restrict__ out) {
    __shared__ __align__(16) float p_s[2][TT];
    __shared__ float wm_s;          // scalar normalizer publish slot (thread 0's d)
    __shared__ float red_s[2];
    __shared__ int   lred[2];
    __shared__ float tsred[2];

    const int b    = blockIdx.x;
    const int tp   = threadIdx.x;     // owned t' column, 0..63
    const int wid  = tp >> 5;
    const int lane = tp & 31;

    const float* emitb = emit + (size_t)b * SS * TT;
    const int*   tagsb = tags + b * SS;

    // ---- decode mask storage dtype from first word (mask[0,0..] are 1s) ----
    const int w0 = ((const int*)mask)[0];
    const int mmode = (w0 == 1) ? MM_I32 : ((w0 == 0x3F800000) ? MM_F32 : MM_U8);

    // ---- sequence length = popcount of prefix mask row ----
    int cnt = 0;
    for (int s = tp; s < SS; s += 64)
        cnt += mask_at(mask, (long long)b * SS + s, mmode);
    #pragma unroll
    for (int o = 16; o; o >>= 1) cnt += __shfl_xor_sync(0xFFFFFFFFu, cnt, o);
    if (lane == 0) lred[wid] = cnt;
    __syncthreads();
    const int len = lred[0] + lred[1];

    // ---- total_score: sum of emit[s, tag_s] + trans[tag_{s-1}, tag_s] over s < len ----
    float ts = 0.0f;
    for (int s = tp; s < len; s += 64) {
        int tg = tagsb[s];
        ts += emitb[(size_t)s * TT + tg];
        if (s > 0) ts += trans[tagsb[s - 1] * TT + tg];
    }
    #pragma unroll
    for (int o = 16; o; o >>= 1) ts += __shfl_xor_sync(0xFFFFFFFFu, ts, o);
    if (lane == 0) tsred[wid] = ts;

    // ---- load E column into registers, packed over t pairs ----
    u64 E2[32];
    #pragma unroll
    for (int j = 0; j < 32; j++) {
        float lo = __expf(trans[(2 * j)     * TT + tp]);
        float hi = __expf(trans[(2 * j + 1) * TT + tp]);
        E2[j] = pack2(lo, hi);
    }

    // ---- init: d0 = emit[b, 0, tp]; exact block max for m0 (one-time cost) ----
    float d0v = emitb[tp];
    {
        float wm = d0v;
        #pragma unroll
        for (int o = 16; o; o >>= 1) wm = fmaxf(wm, __shfl_xor_sync(0xFFFFFFFFu, wm, o));
        if (lane == 0) red_s[wid] = wm;
    }
    __syncthreads();
    const float ts_total = tsred[0] + tsred[1];
    float m_use = fmaxf(red_s[0], red_s[1]);  // m baked into p we are about to write
    float mb    = m_use;                      // m baked into current (readable) p buffer
    float p_val = __expf(d0v - m_use);        // register copy of own p (for final reduce)
    p_s[0][tp] = p_val;
    __syncthreads();                          // publish p_s[0]

    // ---- TRUE distance-8 emit prefetch ring: slot k holds emit for step s with (s-1)&7 == k ----
    float e_buf[8];
    #pragma unroll
    for (int i = 0; i < 8; i++)
        e_buf[i] = (1 + i < len) ? emitb[(size_t)(1 + i) * TT + tp] : 0.0f;

    int buf = 0;
    bool pending = false;

    // one step; KK = (s-1)&7 static in the unrolled loop.
    // PUB: thread 0 publishes its d as the next normalizer (no shfl reduction).
    #define CRF_STEP(S, KK, PREFETCH, PUB)                                           \
    {                                                                                \
        if (pending) { m_use = wm_s; pending = false; }                              \
        float e = e_buf[(KK)];                                                       \
        if (PREFETCH)  /* issue LDG at top of step, overlaps matvec */               \
            e_buf[(KK)] = ((S) + 8 < len) ? emitb[(size_t)((S) + 8) * TT + tp] : 0.0f;\
        float sc = __expf(mb + e - m_use);                                           \
        const ulonglong2* pp = (const ulonglong2*)p_s[buf];                          \
        u64 a0 = 0ull, a1 = 0ull, a2 = 0ull, a3 = 0ull;                              \
        u64 a4 = 0ull, a5 = 0ull, a6 = 0ull, a7 = 0ull;                              \
        _Pragma("unroll")                                                            \
        for (int j = 0; j < 32; j += 8) {                                            \
            ulonglong2 v0 = pp[(j >> 1)];                                            \
            ulonglong2 v1 = pp[(j >> 1) + 1];                                        \
            ulonglong2 v2 = pp[(j >> 1) + 2];                                        \
            ulonglong2 v3 = pp[(j >> 1) + 3];                                        \
            a0 = fma2(v0.x, E2[j],     a0);                                          \
            a1 = fma2(v0.y, E2[j + 1], a1);                                          \
            a2 = fma2(v1.x, E2[j + 2], a2);                                          \
            a3 = fma2(v1.y, E2[j + 3], a3);                                          \
            a4 = fma2(v2.x, E2[j + 4], a4);                                          \
            a5 = fma2(v2.y, E2[j + 5], a5);                                          \
            a6 = fma2(v3.x, E2[j + 6], a6);                                          \
            a7 = fma2(v3.y, E2[j + 7], a7);                                          \
        }                                                                            \
        u64 t0 = add2(a0, a1);                                                       \
        u64 t1 = add2(a2, a3);                                                       \
        u64 t2 = add2(a4, a5);                                                       \
        u64 t3 = add2(a6, a7);                                                       \
        u64 u0 = add2(t0, t1);                                                       \
        u64 u1 = add2(t2, t3);                                                       \
        u64 tt = add2(u0, u1);                                                       \
        float flo, fhi;                                                              \
        unpack2(tt, flo, fhi);                                                       \
        float acc = flo + fhi;                                                       \
        p_val = acc * sc;                                                            \
        p_s[buf ^ 1][tp] = p_val;            /* critical path: acc -> FMUL -> STS */ \
        if (PUB) {                                                                   \
            if (tp == 0) wm_s = mb + __logf(acc) + e;                                \
            pending = true;                                                          \
        }                                                                            \
        __syncthreads();                                                             \
        mb = m_use;                                                                  \
        buf ^= 1;                                                                    \
    }

    int s = 1;
    // main loop: 8 steps per iteration; s always ≡ 1 (mod 8), so slot index is static.
    // Normalizer publish every 4 steps (k==3, k==7), consumed lag-1.
    for (; s + 8 <= len; s += 8) {
        CRF_STEP(s + 0, 0, true, false)
        CRF_STEP(s + 1, 1, true, false)
        CRF_STEP(s + 2, 2, true, false)
        CRF_STEP(s + 3, 3, true, true)
        CRF_STEP(s + 4, 4, true, false)
        CRF_STEP(s + 5, 5, true, false)
        CRF_STEP(s + 6, 6, true, false)
        CRF_STEP(s + 7, 7, true, true)
    }
    // tail: dynamic slot, no prefetch; keep 4-step publish cadence for range safety
    for (; s < len; s++) {
        CRF_STEP(s, (s - 1) & 7, false, ((s & 3) == 0))
    }
    #undef CRF_STEP

    // ---- log_z = mb + log(sum p_last), p_last = exp(d_last - mb) held in registers ----
    float ex = p_val;
    #pragma unroll
    for (int o = 16; o; o >>= 1) ex += __shfl_xor_sync(0xFFFFFFFFu, ex, o);
    if (lane == 0) red_s[wid] = ex;
    __syncthreads();
    if (tp == 0) {
        float logz = mb + __logf(red_s[0] + red_s[1]);
        out[b] = logz - ts_total;   // -(total_score - log_z)
    }
}

extern "C" void kernel_launch(void* const* d_in, const int* in_sizes, int n_in,
                              void* d_out, int out_size) {
    const int*   tags  = (const int*)d_in[0];
    const void*  mask  = d_in[1];
    const float* emit  = (const float*)d_in[2];
    const float* trans = (const float*)d_in[3];
    float* out = (float*)d_out;
    (void)in_sizes; (void)n_in; (void)out_size;

    crf_loss_kernel<<<BB, 64>>>(tags, mask, emit, trans, out);
}

// round 10
// speedup vs baseline: 1.1649x; 1.1649x over previous
#include <cuda_runtime.h>
#include <cuda_bf16.h>

#define BB 512
#define SS 1024
#define TT 64

typedef unsigned long long u64;

// ---- packed f32x2 helpers (Blackwell FFMA2 path) ----
__device__ __forceinline__ u64 fma2(u64 a, u64 b, u64 c) {
    u64 d;
    asm("fma.rn.f32x2 %0, %1, %2, %3;" : "=l"(d) : "l"(a), "l"(b), "l"(c));
    return d;
}
__device__ __forceinline__ u64 add2(u64 a, u64 b) {
    u64 d;
    asm("add.rn.f32x2 %0, %1, %2;" : "=l"(d) : "l"(a), "l"(b));
    return d;
}
__device__ __forceinline__ u64 pack2(float lo, float hi) {
    u64 d;
    asm("mov.b64 %0, {%1, %2};" : "=l"(d) : "f"(lo), "f"(hi));
    return d;
}
__device__ __forceinline__ void unpack2(u64 v, float& lo, float& hi) {
    asm("mov.b64 {%0, %1}, %2;" : "=f"(lo), "=f"(hi) : "l"(v));
}

// mask dtype modes
#define MM_I32 0
#define MM_F32 1
#define MM_U8  2

__device__ __forceinline__ int mask_at(const void* m, long long idx, int mode) {
    if (mode == MM_I32) return ((const int*)m)[idx] != 0;
    if (mode == MM_F32) return ((const float*)m)[idx] != 0.0f;
    return ((const unsigned char*)m)[idx] != 0;
}

// group-local barrier: 64 threads of group g sync on named barrier g+1
#define GBAR() asm volatile("bar.sync %0, 64;" :: "r"(g + 1) : "memory")

__global__ __launch_bounds__(256)
void crf_loss_kernel(const int* __restrict__ tags,
                     const void* __restrict__ mask,
                     const float* __restrict__ emit,
                     const float* __restrict__ trans,
                     float* __restrict__ out) {
    // per-group shared state (4 groups)
    __shared__ __align__(16) float p_s[4][2][TT];
    __shared__ float wm_s[4];       // scalar normalizer publish slot per group
    __shared__ float red_s[4][2];
    __shared__ int   lred[4][2];
    __shared__ float tsred[4][2];

    const int tid  = threadIdx.x;
    const int g    = tid >> 6;        // group 0..3 -> warps {2g,2g+1} -> SMSP pair
    const int tp   = tid & 63;        // owned t' column within group
    const int wid  = tp >> 5;
    const int lane = tp & 31;

    // batch assignment: groups sharing an SMSP pair get (long, short) partners.
    // (g0,g2) share SMSPs {0,1}; (g1,g3) share {2,3}. lengths sorted descending by batch.
    const int bid = blockIdx.x;       // 0..127
    int b;
    if      (g == 0) b = bid;         // ranks   0..127 (longest)
    else if (g == 1) b = 128 + bid;   // ranks 128..255
    else if (g == 2) b = 511 - bid;   // ranks 384..511 (shortest) — pairs with g0
    else             b = 383 - bid;   // ranks 256..383 — pairs with g1

    const float* emitb = emit + (size_t)b * SS * TT;
    const int*   tagsb = tags + b * SS;

    // ---- decode mask storage dtype from first word (mask[0,0..] are 1s) ----
    const int w0 = ((const int*)mask)[0];
    const int mmode = (w0 == 1) ? MM_I32 : ((w0 == 0x3F800000) ? MM_F32 : MM_U8);

    // ---- sequence length = popcount of prefix mask row ----
    int cnt = 0;
    for (int s = tp; s < SS; s += 64)
        cnt += mask_at(mask, (long long)b * SS + s, mmode);
    #pragma unroll
    for (int o = 16; o; o >>= 1) cnt += __shfl_xor_sync(0xFFFFFFFFu, cnt, o);
    if (lane == 0) lred[g][wid] = cnt;
    GBAR();
    const int len = lred[g][0] + lred[g][1];

    // ---- total_score: sum of emit[s, tag_s] + trans[tag_{s-1}, tag_s] over s < len ----
    float ts = 0.0f;
    for (int s = tp; s < len; s += 64) {
        int tg = tagsb[s];
        ts += emitb[(size_t)s * TT + tg];
        if (s > 0) ts += trans[tagsb[s - 1] * TT + tg];
    }
    #pragma unroll
    for (int o = 16; o; o >>= 1) ts += __shfl_xor_sync(0xFFFFFFFFu, ts, o);
    if (lane == 0) tsred[g][wid] = ts;

    // ---- load E column into registers, packed over t pairs ----
    u64 E2[32];
    #pragma unroll
    for (int j = 0; j < 32; j++) {
        float lo = __expf(trans[(2 * j)     * TT + tp]);
        float hi = __expf(trans[(2 * j + 1) * TT + tp]);
        E2[j] = pack2(lo, hi);
    }

    // ---- init: d0 = emit[b, 0, tp]; exact group max for m0 (one-time cost) ----
    float d0v = emitb[tp];
    {
        float wm = d0v;
        #pragma unroll
        for (int o = 16; o; o >>= 1) wm = fmaxf(wm, __shfl_xor_sync(0xFFFFFFFFu, wm, o));
        if (lane == 0) red_s[g][wid] = wm;
    }
    GBAR();
    const float ts_total = tsred[g][0] + tsred[g][1];
    float m_use = fmaxf(red_s[g][0], red_s[g][1]);  // m baked into p about to be written
    float mb    = m_use;                            // m baked into readable p buffer
    float p_val = __expf(d0v - m_use);              // register copy of own p
    p_s[g][0][tp] = p_val;
    GBAR();                                          // publish p_s[g][0]

    // ---- TRUE distance-8 emit prefetch ring: slot k holds emit for step s, (s-1)&7 == k ----
    float e_buf[8];
    #pragma unroll
    for (int i = 0; i < 8; i++)
        e_buf[i] = (1 + i < len) ? emitb[(size_t)(1 + i) * TT + tp] : 0.0f;

    int buf = 0;
    bool pending = false;

    // one step; KK = (s-1)&7 static in the unrolled loop.
    // PUB: thread 0 of the group publishes its d as next normalizer (consumed lag-1).
    #define CRF_STEP(S, KK, PREFETCH, PUB)                                           \
    {                                                                                \
        if (pending) { m_use = wm_s[g]; pending = false; }                           \
        float e = e_buf[(KK)];                                                       \
        if (PREFETCH)  /* issue LDG at top of step, overlaps matvec */               \
            e_buf[(KK)] = ((S) + 8 < len) ? emitb[(size_t)((S) + 8) * TT + tp] : 0.0f;\
        float sc = __expf(mb + e - m_use);                                           \
        const ulonglong2* pp = (const ulonglong2*)p_s[g][buf];                       \
        u64 a0 = 0ull, a1 = 0ull, a2 = 0ull, a3 = 0ull;                              \
        u64 a4 = 0ull, a5 = 0ull, a6 = 0ull, a7 = 0ull;                              \
        _Pragma("unroll")                                                            \
        for (int j = 0; j < 32; j += 8) {                                            \
            ulonglong2 v0 = pp[(j >> 1)];                                            \
            ulonglong2 v1 = pp[(j >> 1) + 1];                                        \
            ulonglong2 v2 = pp[(j >> 1) + 2];                                        \
            ulonglong2 v3 = pp[(j >> 1) + 3];                                        \
            a0 = fma2(v0.x, E2[j],     a0);                                          \
            a1 = fma2(v0.y, E2[j + 1], a1);                                          \
            a2 = fma2(v1.x, E2[j + 2], a2);                                          \
            a3 = fma2(v1.y, E2[j + 3], a3);                                          \
            a4 = fma2(v2.x, E2[j + 4], a4);                                          \
            a5 = fma2(v2.y, E2[j + 5], a5);                                          \
            a6 = fma2(v3.x, E2[j + 6], a6);                                          \
            a7 = fma2(v3.y, E2[j + 7], a7);                                          \
        }                                                                            \
        u64 t0 = add2(a0, a1);                                                       \
        u64 t1 = add2(a2, a3);                                                       \
        u64 t2 = add2(a4, a5);                                                       \
        u64 t3 = add2(a6, a7);                                                       \
        u64 u0 = add2(t0, t1);                                                       \
        u64 u1 = add2(t2, t3);                                                       \
        u64 tt = add2(u0, u1);                                                       \
        float flo, fhi;                                                              \
        unpack2(tt, flo, fhi);                                                       \
        float acc = flo + fhi;                                                       \
        p_val = acc * sc;                                                            \
        p_s[g][buf ^ 1][tp] = p_val;         /* critical path: acc -> FMUL -> STS */ \
        if (PUB) {                                                                   \
            if (tp == 0) wm_s[g] = mb + __logf(acc) + e;                             \
            pending = true;                                                          \
        }                                                                            \
        GBAR();                                                                      \
        mb = m_use;                                                                  \
        buf ^= 1;                                                                    \
    }

    int s = 1;
    // main loop: 8 steps/iter; s ≡ 1 (mod 8), static slot index. Publish every 4 steps.
    for (; s + 8 <= len; s += 8) {
        CRF_STEP(s + 0, 0, true, false)
        CRF_STEP(s + 1, 1, true, false)
        CRF_STEP(s + 2, 2, true, false)
        CRF_STEP(s + 3, 3, true, true)
        CRF_STEP(s + 4, 4, true, false)
        CRF_STEP(s + 5, 5, true, false)
        CRF_STEP(s + 6, 6, true, false)
        CRF_STEP(s + 7, 7, true, true)
    }
    // tail: dynamic slot, no prefetch; keep 4-step publish cadence for range safety
    for (; s < len; s++) {
        CRF_STEP(s, (s - 1) & 7, false, ((s & 3) == 0))
    }
    #undef CRF_STEP

    // ---- log_z = mb + log(sum p_last), p_last = exp(d_last - mb) held in registers ----
    float ex = p_val;
    #pragma unroll
    for (int o = 16; o; o >>= 1) ex += __shfl_xor_sync(0xFFFFFFFFu, ex, o);
    if (lane == 0) red_s[g][wid] = ex;
    GBAR();
    if (tp == 0) {
        float logz = mb + __logf(red_s[g][0] + red_s[g][1]);
        out[b] = logz - ts_total;   // -(total_score - log_z)
    }
}

extern "C" void kernel_launch(void* const* d_in, const int* in_sizes, int n_in,
                              void* d_out, int out_size) {
    const int*   tags  = (const int*)d_in[0];
    const void*  mask  = d_in[1];
    const float* emit  = (const float*)d_in[2];
    const float* trans = (const float*)d_in[3];
    float* out = (float*)d_out;
    (void)in_sizes; (void)n_in; (void)out_size;

    crf_loss_kernel<<<BB / 4, 256>>>(tags, mask, emit, trans, out);
}

// round 11
// speedup vs baseline: 1.2232x; 1.0501x over previous
#include <cuda_runtime.h>
#include <cuda_bf16.h>

#define BB 512
#define SS 1024
#define TT 64

typedef unsigned long long u64;

// ---- packed f32x2 helpers (Blackwell FFMA2 path) ----
__device__ __forceinline__ u64 fma2(u64 a, u64 b, u64 c) {
    u64 d;
    asm("fma.rn.f32x2 %0, %1, %2, %3;" : "=l"(d) : "l"(a), "l"(b), "l"(c));
    return d;
}
__device__ __forceinline__ u64 add2(u64 a, u64 b) {
    u64 d;
    asm("add.rn.f32x2 %0, %1, %2;" : "=l"(d) : "l"(a), "l"(b));
    return d;
}
__device__ __forceinline__ u64 pack2(float lo, float hi) {
    u64 d;
    asm("mov.b64 %0, {%1, %2};" : "=l"(d) : "f"(lo), "f"(hi));
    return d;
}
__device__ __forceinline__ void unpack2(u64 v, float& lo, float& hi) {
    asm("mov.b64 {%0, %1}, %2;" : "=f"(lo), "=f"(hi) : "l"(v));
}

// mask dtype modes
#define MM_I32 0
#define MM_F32 1
#define MM_U8  2

__device__ __forceinline__ int mask_at(const void* m, long long idx, int mode) {
    if (mode == MM_I32) return ((const int*)m)[idx] != 0;
    if (mode == MM_F32) return ((const float*)m)[idx] != 0.0f;
    return ((const unsigned char*)m)[idx] != 0;
}

// group-local barrier: 64 threads of group g sync on named barrier g+1
#define GBAR() asm volatile("bar.sync %0, 64;" :: "r"(g + 1) : "memory")
// pair barrier: 128 threads of groups {2*pair, 2*pair+1}
#define PBAR() asm volatile("bar.sync %0, 128;" :: "r"(pair + 5) : "memory")

__global__ __launch_bounds__(256, 2)
void crf_loss_kernel(const int* __restrict__ tags,
                     const void* __restrict__ mask,
                     const float* __restrict__ emit,
                     const float* __restrict__ trans,
                     float* __restrict__ out) {
    // per-group state (4 groups/block)
    __shared__ __align__(16) float p_s[4][2][TT];
    __shared__ float wm_s[4];         // scalar normalizer publish per group
    __shared__ float red_s[4][2];
    __shared__ int   lred[4][2];
    __shared__ float tsred[2][2];     // per pair (written by fwd group)
    __shared__ float comb_w[2][TT];   // bwd final vector per pair
    __shared__ float comb_mb[2];      // bwd final normalizer per pair

    const int tid  = threadIdx.x;
    const int g    = tid >> 6;        // group 0..3
    const int pair = g >> 1;          // 0: seq A, 1: seq B
    const int bwd  = g & 1;           // 0 = forward half, 1 = backward half
    const int tp   = tid & 63;        // owned state column
    const int wid  = tp >> 5;
    const int lane = tp & 31;

    // seq assignment: pair0 = rank bid (long), pair1 = rank 511-bid (short).
    const int bid = blockIdx.x;       // 0..255
    const int b = (pair == 0) ? bid : (BB - 1 - bid);

    const float* emitb = emit + (size_t)b * SS * TT;
    const int*   tagsb = tags + b * SS;

    // ---- decode mask storage dtype from first word (mask[0,0..] are 1s) ----
    const int w0 = ((const int*)mask)[0];
    const int mmode = (w0 == 1) ? MM_I32 : ((w0 == 0x3F800000) ? MM_F32 : MM_U8);

    // ---- sequence length = popcount of prefix mask row ----
    int cnt = 0;
    for (int s = tp; s < SS; s += 64)
        cnt += mask_at(mask, (long long)b * SS + s, mmode);
    #pragma unroll
    for (int o = 16; o; o >>= 1) cnt += __shfl_xor_sync(0xFFFFFFFFu, cnt, o);
    if (lane == 0) lred[g][wid] = cnt;
    GBAR();
    const int len = lred[g][0] + lred[g][1];

    // split point: fwd covers steps 1..Mf, bwd covers Mb steps from the far end
    const int m  = (len - 1) >> 1;
    const int M  = bwd ? (len - 1 - m) : m;     // my step count
    const int strd = bwd ? -TT : TT;
    const float* eP = emitb + (size_t)(bwd ? (len - 1) : 0) * TT + tp;  // e at step j: eP[j*strd]

    // ---- total_score (fwd group only) ----
    if (!bwd) {
        float ts = 0.0f;
        for (int s = tp; s < len; s += 64) {
            int tg = tagsb[s];
            ts += emitb[(size_t)s * TT + tg];
            if (s > 0) ts += trans[tagsb[s - 1] * TT + tg];
        }
        #pragma unroll
        for (int o = 16; o; o >>= 1) ts += __shfl_xor_sync(0xFFFFFFFFu, ts, o);
        if (lane == 0) tsred[pair][wid] = ts;
    }

    // ---- E operand in registers, packed over pairs.
    // fwd: column tp over row pairs {E[2j][tp], E[2j+1][tp]}
    // bwd: row tp over column pairs {E[tp][2j], E[tp][2j+1]}
    u64 E2[32];
    #pragma unroll
    for (int j = 0; j < 32; j++) {
        float lo, hi;
        if (!bwd) {
            lo = __expf(trans[(2 * j)     * TT + tp]);
            hi = __expf(trans[(2 * j + 1) * TT + tp]);
        } else {
            lo = __expf(trans[tp * TT + 2 * j]);
            hi = __expf(trans[tp * TT + 2 * j + 1]);
        }
        E2[j] = pack2(lo, hi);
    }

    // ---- init: v0 = exp(e0 - m0), m0 = exact group max of e0 ----
    float d0v = eP[0];
    {
        float wm = d0v;
        #pragma unroll
        for (int o = 16; o; o >>= 1) wm = fmaxf(wm, __shfl_xor_sync(0xFFFFFFFFu, wm, o));
        if (lane == 0) red_s[g][wid] = wm;
    }
    GBAR();
    float m_use = fmaxf(red_s[g][0], red_s[g][1]);
    float mb    = m_use;
    float p_val = __expf(d0v - m_use);
    p_s[g][0][tp] = p_val;
    GBAR();                           // publish p_s[g][0]

    // ---- distance-8 emit prefetch ring: slot k holds e for step s with (s-1)&7==k ----
    float e_buf[8];
    #pragma unroll
    for (int i = 0; i < 8; i++)
        e_buf[i] = (1 + i <= M) ? eP[(long long)(1 + i) * strd] : 0.0f;

    int buf = 0;
    bool pending = false;

    // one step (identical for fwd/bwd); KK=(s-1)&7 static in unrolled loop.
    #define CRF_STEP(S, KK, PREFETCH, PUB)                                           \
    {                                                                                \
        if (pending) { m_use = wm_s[g]; pending = false; }                           \
        float e = e_buf[(KK)];                                                       \
        if (PREFETCH)                                                                \
            e_buf[(KK)] = ((S) + 8 <= M) ? eP[(long long)((S) + 8) * strd] : 0.0f;   \
        float sc = __expf(mb + e - m_use);                                           \
        const ulonglong2* pp = (const ulonglong2*)p_s[g][buf];                       \
        u64 a0 = 0ull, a1 = 0ull, a2 = 0ull, a3 = 0ull;                              \
        u64 a4 = 0ull, a5 = 0ull, a6 = 0ull, a7 = 0ull;                              \
        _Pragma("unroll")                                                            \
        for (int j = 0; j < 32; j += 8) {                                            \
            ulonglong2 v0 = pp[(j >> 1)];                                            \
            ulonglong2 v1 = pp[(j >> 1) + 1];                                        \
            ulonglong2 v2 = pp[(j >> 1) + 2];                                        \
            ulonglong2 v3 = pp[(j >> 1) + 3];                                        \
            a0 = fma2(v0.x, E2[j],     a0);                                          \
            a1 = fma2(v0.y, E2[j + 1], a1);                                          \
            a2 = fma2(v1.x, E2[j + 2], a2);                                          \
            a3 = fma2(v1.y, E2[j + 3], a3);                                          \
            a4 = fma2(v2.x, E2[j + 4], a4);                                          \
            a5 = fma2(v2.y, E2[j + 5], a5);                                          \
            a6 = fma2(v3.x, E2[j + 6], a6);                                          \
            a7 = fma2(v3.y, E2[j + 7], a7);                                          \
        }                                                                            \
        u64 t0 = add2(a0, a1);                                                       \
        u64 t1 = add2(a2, a3);                                                       \
        u64 t2 = add2(a4, a5);                                                       \
        u64 t3 = add2(a6, a7);                                                       \
        u64 u0 = add2(t0, t1);                                                       \
        u64 u1 = add2(t2, t3);                                                       \
        u64 tt = add2(u0, u1);                                                       \
        float flo, fhi;                                                              \
        unpack2(tt, flo, fhi);                                                       \
        float acc = flo + fhi;                                                       \
        p_val = acc * sc;                                                            \
        p_s[g][buf ^ 1][tp] = p_val;                                                 \
        if (PUB) {                                                                   \
            if (tp == 0) wm_s[g] = mb + __logf(acc) + e;                             \
            pending = true;                                                          \
        }                                                                            \
        GBAR();                                                                      \
        mb = m_use;                                                                  \
        buf ^= 1;                                                                    \
    }

    int s = 1;
    for (; s + 7 <= M; s += 8) {
        CRF_STEP(s + 0, 0, true, false)
        CRF_STEP(s + 1, 1, true, false)
        CRF_STEP(s + 2, 2, true, false)
        CRF_STEP(s + 3, 3, true, true)
        CRF_STEP(s + 4, 4, true, false)
        CRF_STEP(s + 5, 5, true, false)
        CRF_STEP(s + 6, 6, true, false)
        CRF_STEP(s + 7, 7, true, true)
    }
    for (; s <= M; s++) {
        CRF_STEP(s, (s - 1) & 7, false, ((s & 3) == 0))
    }
    #undef CRF_STEP

    // ---- combine halves: log Z = mbf + mbw + log sum_t pf[t]*pw[t]*exp(-e_m[t]) ----
    if (bwd) {
        comb_w[pair][tp] = p_val;     // pw = exp(gamma_Mb - mbw), gamma = e + beta
        if (tp == 0) comb_mb[pair] = mb;
    }
    PBAR();
    if (!bwd) {
        float em = emitb[(size_t)m * TT + tp];
        float prod = p_val * comb_w[pair][tp] * __expf(-em);
        #pragma unroll
        for (int o = 16; o; o >>= 1) prod += __shfl_xor_sync(0xFFFFFFFFu, prod, o);
        if (lane == 0) red_s[g][wid] = prod;
        GBAR();
        if (tp == 0) {
            float logz = mb + comb_mb[pair] + __logf(red_s[g][0] + red_s[g][1]);
            float ts_total = tsred[pair][0] + tsred[pair][1];
            out[b] = logz - ts_total;   // -(total_score - log_z)
        }
    }
}

extern "C" void kernel_launch(void* const* d_in, const int* in_sizes, int n_in,
                              void* d_out, int out_size) {
    const int*   tags  = (const int*)d_in[0];
    const void*  mask  = d_in[1];
    const float* emit  = (const float*)d_in[2];
    const float* trans = (const float*)d_in[3];
    float* out = (float*)d_out;
    (void)in_sizes; (void)n_in; (void)out_size;

    crf_loss_kernel<<<BB / 2, 256>>>(tags, mask, emit, trans, out);
}